// round 3
// baseline (speedup 1.0000x reference)
#include <cuda_runtime.h>
#include <cuda_bf16.h>

// Problem constants (fixed shapes per reference)
#define E_TOTAL   3200000
#define NN        100000
#define EDGE_DIM  64
#define ADDED     24
#define H_DIM     256
#define KDIM      280
#define OUT_DIM   256

// Scatter-sum scratch: [NN, ADDED] fp32 = 9.6 MB.
// Zero-initialized at module load; kernel B re-zeroes rows after consuming
// them, preserving the invariant across graph replays.
__device__ float g_ah[NN * ADDED];

// ---------------- packed f32x2 helpers ----------------
__device__ __forceinline__ unsigned long long pack2(float lo, float hi) {
    unsigned long long r;
    asm("mov.b64 %0, {%1, %2};" : "=l"(r) : "f"(lo), "f"(hi));
    return r;
}
__device__ __forceinline__ void unpack2(unsigned long long v, float& lo, float& hi) {
    asm("mov.b64 {%0, %1}, %2;" : "=f"(lo), "=f"(hi) : "l"(v));
}
// Packed dual fp32 FMA (sm_103a FFMA2): d = a*b + c on both 32-bit halves.
__device__ __forceinline__ unsigned long long ffma2(unsigned long long a,
                                                    unsigned long long b,
                                                    unsigned long long c) {
    unsigned long long d;
    asm("fma.rn.f32x2 %0, %1, %2, %3;" : "=l"(d) : "l"(a), "l"(b), "l"(c));
    return d;
}
// Vectorized global float reduction: one REDG for 4 floats.
__device__ __forceinline__ void red_add_v4(float* p, float a, float b, float c, float d) {
    asm volatile("red.global.add.v4.f32 [%0], {%1, %2, %3, %4};"
                 :: "l"(p), "f"(a), "f"(b), "f"(c), "f"(d) : "memory");
}

// ============================================================================
// Kernel A (fused): edge-projection+scatter blocks AND h-part GEMM blocks in
// one grid. Blocks with blockIdx.x % 3 == 0 are GEMM blocks (3126 of them:
// 1563 row tiles x 2 col tiles); the rest are edge blocks (6250, 512 edges
// each). The two block types use disjoint pipes (LSU/L2-atomics vs FMA/LDS)
// and have no data dependence, so co-residency overlaps them.
// ============================================================================

#define GEMM_ROW_TILES 1563              // ceil(NN/64)
#define N_GEMM_BLOCKS  (GEMM_ROW_TILES * 2)
#define N_EDGE_BLOCKS  (E_TOTAL / 512)   // 6250
#define N_A_BLOCKS     (N_GEMM_BLOCKS + N_EDGE_BLOCKS)  // 9376

__global__ __launch_bounds__(256, 2) void fused_kernel(
    const float* __restrict__ edge_feat,   // [E, 64]
    const float* __restrict__ W_msg,       // [64, 24]
    const float* __restrict__ b_msg,       // [24]
    const int*   __restrict__ dst_idx,     // [E]
    const float* __restrict__ h,           // [NN, 256]
    const float* __restrict__ W1,          // [280, 256]
    float* __restrict__ out)               // [NN, 256] (partial, no bias/relu)
{
    __shared__ __align__(16) unsigned char sm[6784];
    const int tid = threadIdx.x;
    const int b = blockIdx.x;

    if (b % 3 == 0) {
        // ------------------- GEMM block: out_tile = h_tile @ W1[0:256] ------
        const int gb = b / 3;              // 0 .. 3125
        const int rt = gb >> 1;            // row tile 0..1562
        const int cb = gb & 1;             // col half 0..1
        const int row0 = rt * 64;

        float (*ws)[128] = reinterpret_cast<float(*)[128]>(sm);          // 4096 B
        float (*xs)[10]  = reinterpret_cast<float(*)[10]>(sm + 4096);    // 2560 B

        const int tx = tid & 15;   // col group (16)
        const int ty = tid >> 4;   // row group (16) -> 4 rows each

        unsigned long long acc[4][4];
#pragma unroll
        for (int i = 0; i < 4; i++)
#pragma unroll
            for (int c = 0; c < 4; c++) acc[i][c] = 0ULL;

        const int lr = tid >> 2;          // 0..63  (x-loader row)
        const int lk = (tid & 3) * 2;     // 0,2,4,6 (x-loader k pair)

        for (int kt = 0; kt < H_DIM / 8; kt++) {   // 32 k-tiles (h part only)
            const int kbase = kt * 8;
            // W tile: rows kbase..+7, cols cb*128..+127 -> 256 float4, 1/thread
            {
                const int r = tid >> 5;         // 0..7
                const int c4 = tid & 31;        // 0..31
                const float4 v = *reinterpret_cast<const float4*>(
                    W1 + (long long)(kbase + r) * OUT_DIM + cb * 128 + 4 * c4);
                *reinterpret_cast<float4*>(&ws[r][4 * c4]) = v;
            }
            // x tile: 64 rows x 8 k, one float2 per thread (pure h, k<256)
            {
                const int row = row0 + lr;
                float2 v = make_float2(0.f, 0.f);
                if (row < NN)
                    v = *reinterpret_cast<const float2*>(
                        h + (long long)row * H_DIM + kbase + lk);
                xs[lr][lk] = v.x;
                xs[lr][lk + 1] = v.y;
            }
            __syncthreads();

#pragma unroll
            for (int k = 0; k < 8; k++) {
                unsigned long long a[4];
#pragma unroll
                for (int i = 0; i < 4; i++) {
                    float av = xs[ty * 4 + i][k];
                    a[i] = pack2(av, av);
                }
#pragma unroll
                for (int c = 0; c < 4; c++) {
                    unsigned long long w = *reinterpret_cast<const unsigned long long*>(
                        &ws[k][2 * (tx + 16 * c)]);
#pragma unroll
                    for (int i = 0; i < 4; i++) acc[i][c] = ffma2(a[i], w, acc[i][c]);
                }
            }
            __syncthreads();
        }

        // store partial (no bias, no relu)
#pragma unroll
        for (int c = 0; c < 4; c++) {
            const int col = cb * 128 + 2 * (tx + 16 * c);
#pragma unroll
            for (int i = 0; i < 4; i++) {
                const int row = row0 + ty * 4 + i;
                if (row < NN) {
                    float x0, x1;
                    unpack2(acc[i][c], x0, x1);
                    *reinterpret_cast<float2*>(out + (long long)row * OUT_DIM + col) =
                        make_float2(x0, x1);
                }
            }
        }
    } else {
        // ------------------- EDGE block: project 512 edges + scatter --------
        const int eb = b - b / 3 - 1;      // 0 .. 6249
        if (eb >= N_EDGE_BLOCKS) return;

        unsigned long long (*Wp)[12] =
            reinterpret_cast<unsigned long long(*)[12]>(sm);             // 6144 B
        unsigned long long* bp =
            reinterpret_cast<unsigned long long*>(sm + 6144);            // 96 B

        for (int idx = tid; idx < EDGE_DIM * (ADDED / 2); idx += 256) {
            int k = idx / (ADDED / 2);
            int j = idx % (ADDED / 2);
            Wp[k][j] = pack2(W_msg[k * ADDED + 2 * j], W_msg[k * ADDED + 2 * j + 1]);
        }
        if (tid < ADDED / 2) bp[tid] = pack2(b_msg[2 * tid], b_msg[2 * tid + 1]);
        __syncthreads();

        const long long base = (long long)eb * 512 + tid;   // 2 edges/thread
        const long long e0 = base;
        const long long e1 = base + 256;

        const float4* f0 = reinterpret_cast<const float4*>(edge_feat) + e0 * (EDGE_DIM / 4);
        const float4* f1 = reinterpret_cast<const float4*>(edge_feat) + e1 * (EDGE_DIM / 4);

        unsigned long long acc0[ADDED / 2], acc1[ADDED / 2];
#pragma unroll
        for (int j = 0; j < ADDED / 2; j++) { acc0[j] = bp[j]; acc1[j] = bp[j]; }

#pragma unroll
        for (int k4 = 0; k4 < EDGE_DIM / 4; k4++) {
            float4 va = f0[k4];
            float4 vb = f1[k4];
            float ea[4] = {va.x, va.y, va.z, va.w};
            float eb4[4] = {vb.x, vb.y, vb.z, vb.w};
#pragma unroll
            for (int s = 0; s < 4; s++) {
                int k = k4 * 4 + s;
                unsigned long long pa = pack2(ea[s], ea[s]);
                unsigned long long pb = pack2(eb4[s], eb4[s]);
#pragma unroll
                for (int j = 0; j < ADDED / 2; j++) {
                    unsigned long long w = Wp[k][j];
                    acc0[j] = ffma2(pa, w, acc0[j]);
                    acc1[j] = ffma2(pb, w, acc1[j]);
                }
            }
        }

        const int d0 = dst_idx[e0];
        const int d1 = dst_idx[e1];
        float* p0 = g_ah + (long long)d0 * ADDED;
        float* p1 = g_ah + (long long)d1 * ADDED;
#pragma unroll
        for (int q = 0; q < ADDED / 4; q++) {
            float x0, x1, x2, x3;
            unpack2(acc0[2 * q],     x0, x1);
            unpack2(acc0[2 * q + 1], x2, x3);
            red_add_v4(p0 + 4 * q, x0, x1, x2, x3);
        }
#pragma unroll
        for (int q = 0; q < ADDED / 4; q++) {
            float y0, y1, y2, y3;
            unpack2(acc1[2 * q],     y0, y1);
            unpack2(acc1[2 * q + 1], y2, y3);
            red_add_v4(p1 + 4 * q, y0, y1, y2, y3);
        }
    }
}

// ============================================================================
// Kernel B: out = relu(out_partial + (g_ah * norm) @ W1[256:280] + b1)
// Also re-zeroes g_ah rows for the next graph replay.
// Block: 128 nodes x 256 cols, 256 threads (cp = tid&127 -> col pair,
// half = tid>>7 -> 64 rows each).
// ============================================================================
__global__ __launch_bounds__(256, 4) void tail_kernel(
    const float* __restrict__ norm,   // [NN, 1]
    const float* __restrict__ W1,     // [280, 256]
    const float* __restrict__ b1,     // [256]
    float* __restrict__ out)          // [NN, 256]
{
    __shared__ __align__(16) float s_ah[128][ADDED];   // 12 KB (norm-scaled)

    const int tid = threadIdx.x;
    const int r0 = blockIdx.x * 128;

    // load g_ah tile * norm into smem (768 float4), then zero g_ah tile
    {
        const int nf4 = 128 * ADDED / 4;   // 768
        for (int i = tid; i < nf4; i += 256) {
            const int row = i / (ADDED / 4);
            const int grow = r0 + row;
            float4 v = make_float4(0.f, 0.f, 0.f, 0.f);
            if (grow < NN) {
                v = reinterpret_cast<const float4*>(g_ah)[(long long)grow * (ADDED / 4)
                                                          + (i % (ADDED / 4))];
                const float nr = norm[grow];
                v.x *= nr; v.y *= nr; v.z *= nr; v.w *= nr;
            }
            reinterpret_cast<float4*>(&s_ah[0][0])[i] = v;
        }
        __syncthreads();
        // re-zero consumed rows
        for (int i = tid; i < nf4; i += 256) {
            const int grow = r0 + i / (ADDED / 4);
            if (grow < NN)
                reinterpret_cast<float4*>(g_ah)[(long long)grow * (ADDED / 4)
                                                + (i % (ADDED / 4))] =
                    make_float4(0.f, 0.f, 0.f, 0.f);
        }
    }

    const int cp = tid & 127;        // col pair -> cols 2cp, 2cp+1
    const int half = tid >> 7;       // 0..1 -> rows half*64..+63

    // this thread's W1-tail column pair: 24 packed values
    unsigned long long wcol[ADDED];
#pragma unroll
    for (int k = 0; k < ADDED; k++) {
        wcol[k] = *reinterpret_cast<const unsigned long long*>(
            W1 + (long long)(H_DIM + k) * OUT_DIM + 2 * cp);
    }
    const unsigned long long bb = *reinterpret_cast<const unsigned long long*>(b1 + 2 * cp);

    for (int r = 0; r < 64; r++) {
        const int lrow = half * 64 + r;
        const int row = r0 + lrow;
        if (row >= NN) break;
        unsigned long long acc = bb;
#pragma unroll
        for (int k = 0; k < ADDED; k++) {
            const float a = s_ah[lrow][k];
            acc = ffma2(pack2(a, a), wcol[k], acc);
        }
        float2* po = reinterpret_cast<float2*>(out + (long long)row * OUT_DIM + 2 * cp);
        const float2 part = *po;
        float t0, t1;
        unpack2(acc, t0, t1);
        t0 = fmaxf(part.x + t0, 0.f);
        t1 = fmaxf(part.y + t1, 0.f);
        *po = make_float2(t0, t1);
    }
}

// ---------------- launch ----------------
extern "C" void kernel_launch(void* const* d_in, const int* in_sizes, int n_in,
                              void* d_out, int out_size) {
    const float* h         = (const float*)d_in[0];
    const float* edge_feat = (const float*)d_in[1];
    const float* norm      = (const float*)d_in[2];
    const float* W_msg     = (const float*)d_in[3];
    const float* b_msg     = (const float*)d_in[4];
    const float* W1        = (const float*)d_in[5];
    const float* b1        = (const float*)d_in[6];
    const int*   dst_idx   = (const int*)d_in[7];
    float* out = (float*)d_out;

    // A: fused edge scatter + h-part GEMM (overlapped block types)
    fused_kernel<<<N_A_BLOCKS, 256>>>(edge_feat, W_msg, b_msg, dst_idx, h, W1, out);

    // B: tail GEMM + bias + ReLU (+ g_ah re-zero)
    tail_kernel<<<(NN + 127) / 128, 256>>>(norm, W1, b1, out);
}

// round 4
// speedup vs baseline: 1.2509x; 1.2509x over previous
#include <cuda_runtime.h>
#include <cuda_bf16.h>

// Problem constants (fixed shapes per reference)
#define E_TOTAL   3200000
#define NN        100000
#define EDGE_DIM  64
#define ADDED     24
#define H_DIM     256
#define KDIM      280
#define OUT_DIM   256

// Scatter-sum scratch: [NN, ADDED] fp32 = 9.6 MB.
// Zero-initialized at module load; node_kernel re-zeroes rows after consuming
// them, preserving the invariant across graph replays.
__device__ float g_ah[NN * ADDED];

// ---------------- packed f32x2 helpers (edge kernel) ----------------
__device__ __forceinline__ unsigned long long pack2(float lo, float hi) {
    unsigned long long r;
    asm("mov.b64 %0, {%1, %2};" : "=l"(r) : "f"(lo), "f"(hi));
    return r;
}
__device__ __forceinline__ void unpack2(unsigned long long v, float& lo, float& hi) {
    asm("mov.b64 {%0, %1}, %2;" : "=f"(lo), "=f"(hi) : "l"(v));
}
__device__ __forceinline__ unsigned long long ffma2(unsigned long long a,
                                                    unsigned long long b,
                                                    unsigned long long c) {
    unsigned long long d;
    asm("fma.rn.f32x2 %0, %1, %2, %3;" : "=l"(d) : "l"(a), "l"(b), "l"(c));
    return d;
}
__device__ __forceinline__ void red_add_v4(float* p, float a, float b, float c, float d) {
    asm volatile("red.global.add.v4.f32 [%0], {%1, %2, %3, %4};"
                 :: "l"(p), "f"(a), "f"(b), "f"(c), "f"(d) : "memory");
}
// fp32 -> tf32 bits (round-to-nearest-away)
__device__ __forceinline__ unsigned cvt_tf32(float f) {
    unsigned u;
    asm("cvt.rna.tf32.f32 %0, %1;" : "=r"(u) : "f"(f));
    return u;
}
// tf32 mma: D(16x8) += A(16x8) * B(8x8), fp32 accumulate
__device__ __forceinline__ void mma_tf32(float& d0, float& d1, float& d2, float& d3,
                                         unsigned a0, unsigned a1, unsigned a2, unsigned a3,
                                         unsigned b0, unsigned b1) {
    asm volatile(
        "mma.sync.aligned.m16n8k8.row.col.f32.tf32.tf32.f32 "
        "{%0,%1,%2,%3}, {%4,%5,%6,%7}, {%8,%9}, {%0,%1,%2,%3};"
        : "+f"(d0), "+f"(d1), "+f"(d2), "+f"(d3)
        : "r"(a0), "r"(a1), "r"(a2), "r"(a3), "r"(b0), "r"(b1));
}

// ============================================================================
// Kernel 1: edge projection + scatter-add (unchanged from R2; REDG-bound)
// ============================================================================
__global__ __launch_bounds__(256) void edge_kernel(
    const float* __restrict__ edge_feat,   // [E, 64]
    const float* __restrict__ W_msg,       // [64, 24]
    const float* __restrict__ b_msg,       // [24]
    const int*   __restrict__ dst_idx)     // [E]
{
    __shared__ unsigned long long Wp[EDGE_DIM][ADDED / 2];
    __shared__ unsigned long long bp[ADDED / 2];

    const int tid = threadIdx.x;
    for (int idx = tid; idx < EDGE_DIM * (ADDED / 2); idx += blockDim.x) {
        int k = idx / (ADDED / 2);
        int j = idx % (ADDED / 2);
        Wp[k][j] = pack2(W_msg[k * ADDED + 2 * j], W_msg[k * ADDED + 2 * j + 1]);
    }
    if (tid < ADDED / 2) bp[tid] = pack2(b_msg[2 * tid], b_msg[2 * tid + 1]);
    __syncthreads();

    const long long gid = (long long)blockIdx.x * blockDim.x + tid;
    const long long e0 = gid;
    const long long e1 = gid + (E_TOTAL / 2);
    if (e0 >= E_TOTAL / 2) return;

    const float4* f0 = reinterpret_cast<const float4*>(edge_feat) + e0 * (EDGE_DIM / 4);
    const float4* f1 = reinterpret_cast<const float4*>(edge_feat) + e1 * (EDGE_DIM / 4);

    unsigned long long acc0[ADDED / 2], acc1[ADDED / 2];
#pragma unroll
    for (int j = 0; j < ADDED / 2; j++) { acc0[j] = bp[j]; acc1[j] = bp[j]; }

#pragma unroll
    for (int k4 = 0; k4 < EDGE_DIM / 4; k4++) {
        float4 va = f0[k4];
        float4 vb = f1[k4];
        float ea[4] = {va.x, va.y, va.z, va.w};
        float eb[4] = {vb.x, vb.y, vb.z, vb.w};
#pragma unroll
        for (int s = 0; s < 4; s++) {
            int k = k4 * 4 + s;
            unsigned long long pa = pack2(ea[s], ea[s]);
            unsigned long long pb = pack2(eb[s], eb[s]);
#pragma unroll
            for (int j = 0; j < ADDED / 2; j++) {
                unsigned long long w = Wp[k][j];
                acc0[j] = ffma2(pa, w, acc0[j]);
                acc1[j] = ffma2(pb, w, acc1[j]);
            }
        }
    }

    const int d0 = dst_idx[e0];
    const int d1 = dst_idx[e1];
    float* p0 = g_ah + (long long)d0 * ADDED;
    float* p1 = g_ah + (long long)d1 * ADDED;
#pragma unroll
    for (int q = 0; q < ADDED / 4; q++) {
        float x0, x1, x2, x3;
        unpack2(acc0[2 * q],     x0, x1);
        unpack2(acc0[2 * q + 1], x2, x3);
        red_add_v4(p0 + 4 * q, x0, x1, x2, x3);
    }
#pragma unroll
    for (int q = 0; q < ADDED / 4; q++) {
        float y0, y1, y2, y3;
        unpack2(acc1[2 * q],     y0, y1);
        unpack2(acc1[2 * q + 1], y2, y3);
        red_add_v4(p1 + 4 * q, y0, y1, y2, y3);
    }
}

// ============================================================================
// Kernel 2: node GEMM via tf32 mma.sync, full K=280 (h ++ g_ah*norm),
// bias + ReLU epilogue, g_ah re-zero. Block = 128 rows x 256 cols,
// 512 threads = 16 warps (4 m-warps x 4 n-warps; warp tile 32x64).
// ============================================================================
#define NODE_BLOCKS 782   // 782*128 = 100096 >= NN

__global__ __launch_bounds__(512, 1) void node_kernel(
    const float* __restrict__ h,      // [NN, 256]
    const float* __restrict__ norm,   // [NN, 1]
    const float* __restrict__ W1,     // [280, 256]
    const float* __restrict__ b1,     // [256]
    float* __restrict__ out)          // [NN, 256]
{
    // tf32 bit arrays; padded so fragment LDS patterns are bank-conflict-free
    __shared__ unsigned as_[8][136];   // A: [k][row] (transposed)
    __shared__ unsigned ws_[8][264];   // B: [k][col]

    const int tid = threadIdx.x;
    const int wid = tid >> 5;
    const int lane = tid & 31;
    const int g  = lane >> 2;    // groupID 0..7
    const int tg = lane & 3;     // threadInGroup 0..3
    const int wm = wid & 3;      // m-warp: rows wm*32 .. +31
    const int wn = wid >> 2;     // n-warp: cols wn*64 .. +63
    const int row0 = blockIdx.x * 128;

    float acc[2][8][4];
#pragma unroll
    for (int mt = 0; mt < 2; mt++)
#pragma unroll
        for (int nf = 0; nf < 8; nf++)
#pragma unroll
            for (int i = 0; i < 4; i++) acc[mt][nf][i] = 0.f;

    // loader roles
    const int br = tid >> 6;           // B: k-row 0..7
    const int bc = (tid & 63) * 4;     // B: col 0..252
    const int ar = (tid >> 1) & 127;   // A: row 0..127 (threads < 256)
    const int ap = (tid & 1) * 4;      // A: k offset 0 or 4

    for (int kt = 0; kt < KDIM / 8; kt++) {   // 35 iterations
        const int k0 = kt * 8;

        // ---- load B tile: W1[k0..k0+7][0..255] -> tf32 bits
        {
            const float4 w = *reinterpret_cast<const float4*>(
                W1 + (long long)(k0 + br) * OUT_DIM + bc);
            uint4 u;
            u.x = cvt_tf32(w.x); u.y = cvt_tf32(w.y);
            u.z = cvt_tf32(w.z); u.w = cvt_tf32(w.w);
            *reinterpret_cast<uint4*>(&ws_[br][bc]) = u;
        }
        // ---- load A tile: x[row0..row0+127][k0..k0+7] -> tf32, transposed
        if (tid < 256) {
            const int grow = row0 + ar;
            float4 v = make_float4(0.f, 0.f, 0.f, 0.f);
            if (grow < NN) {
                if (k0 < H_DIM) {
                    v = *reinterpret_cast<const float4*>(
                        h + (long long)grow * H_DIM + k0 + ap);
                } else {
                    v = *reinterpret_cast<const float4*>(
                        g_ah + (long long)grow * ADDED + (k0 - H_DIM) + ap);
                    const float nr = norm[grow];
                    v.x *= nr; v.y *= nr; v.z *= nr; v.w *= nr;
                }
            }
            as_[ap + 0][ar] = cvt_tf32(v.x);
            as_[ap + 1][ar] = cvt_tf32(v.y);
            as_[ap + 2][ar] = cvt_tf32(v.z);
            as_[ap + 3][ar] = cvt_tf32(v.w);
        }
        __syncthreads();

        // ---- compute: 2 m-tiles x 8 n-frags of m16n8k8
#pragma unroll
        for (int mt = 0; mt < 2; mt++) {
            const int rb = wm * 32 + mt * 16;
            const unsigned a0 = as_[tg][rb + g];
            const unsigned a1 = as_[tg][rb + g + 8];
            const unsigned a2 = as_[tg + 4][rb + g];
            const unsigned a3 = as_[tg + 4][rb + g + 8];
#pragma unroll
            for (int nf = 0; nf < 8; nf++) {
                const int cb = wn * 64 + nf * 8;
                const unsigned b0 = ws_[tg][cb + g];
                const unsigned b1v = ws_[tg + 4][cb + g];
                mma_tf32(acc[mt][nf][0], acc[mt][nf][1], acc[mt][nf][2], acc[mt][nf][3],
                         a0, a1, a2, a3, b0, b1v);
            }
        }
        __syncthreads();
    }

    // ---- re-zero this block's g_ah rows (all reads completed above)
    {
        const int nf4 = 128 * (ADDED / 4);   // 768 float4
        for (int i = tid; i < nf4; i += 512) {
            const int grow = row0 + i / (ADDED / 4);
            if (grow < NN)
                reinterpret_cast<float4*>(g_ah)[(long long)grow * (ADDED / 4)
                                                + (i % (ADDED / 4))] =
                    make_float4(0.f, 0.f, 0.f, 0.f);
        }
    }

    // ---- epilogue: bias + relu + store
#pragma unroll
    for (int nf = 0; nf < 8; nf++) {
        const int col = wn * 64 + nf * 8 + 2 * tg;
        const float2 bb = *reinterpret_cast<const float2*>(b1 + col);
#pragma unroll
        for (int mt = 0; mt < 2; mt++) {
            const int r = row0 + wm * 32 + mt * 16 + g;
            if (r < NN) {
                float2 o;
                o.x = fmaxf(acc[mt][nf][0] + bb.x, 0.f);
                o.y = fmaxf(acc[mt][nf][1] + bb.y, 0.f);
                *reinterpret_cast<float2*>(out + (long long)r * OUT_DIM + col) = o;
            }
            const int r2 = r + 8;
            if (r2 < NN) {
                float2 o;
                o.x = fmaxf(acc[mt][nf][2] + bb.x, 0.f);
                o.y = fmaxf(acc[mt][nf][3] + bb.y, 0.f);
                *reinterpret_cast<float2*>(out + (long long)r2 * OUT_DIM + col) = o;
            }
        }
    }
}

// ---------------- launch ----------------
extern "C" void kernel_launch(void* const* d_in, const int* in_sizes, int n_in,
                              void* d_out, int out_size) {
    const float* h         = (const float*)d_in[0];
    const float* edge_feat = (const float*)d_in[1];
    const float* norm      = (const float*)d_in[2];
    const float* W_msg     = (const float*)d_in[3];
    const float* b_msg     = (const float*)d_in[4];
    const float* W1        = (const float*)d_in[5];
    const float* b1        = (const float*)d_in[6];
    const int*   dst_idx   = (const int*)d_in[7];
    float* out = (float*)d_out;

    // 1. edge projection + scatter
    edge_kernel<<<(E_TOTAL / 2) / 256, 256>>>(edge_feat, W_msg, b_msg, dst_idx);

    // 2. node GEMM (tf32 tensor cores, full K=280) + bias + ReLU + g_ah re-zero
    node_kernel<<<NODE_BLOCKS, 512>>>(h, norm, W1, b1, out);
}

// round 5
// speedup vs baseline: 1.4320x; 1.1448x over previous
#include <cuda_runtime.h>
#include <cuda_bf16.h>

// Problem constants (fixed shapes per reference)
#define E_TOTAL   3200000
#define NN        100000
#define EDGE_DIM  64
#define ADDED     24
#define H_DIM     256
#define KDIM      280
#define OUT_DIM   256

// Scatter-sum scratch: [NN, ADDED] fp32 = 9.6 MB.
// Zero-initialized at module load; node_kernel re-zeroes rows after consuming
// them, preserving the invariant across graph replays.
__device__ float g_ah[NN * ADDED];

// ---------------- helpers ----------------
__device__ __forceinline__ void red_add_v4(float* p, float a, float b, float c, float d) {
    asm volatile("red.global.add.v4.f32 [%0], {%1, %2, %3, %4};"
                 :: "l"(p), "f"(a), "f"(b), "f"(c), "f"(d) : "memory");
}
// fp32 -> tf32 bits (round-to-nearest-away)
__device__ __forceinline__ unsigned cvt_tf32(float f) {
    unsigned u;
    asm("cvt.rna.tf32.f32 %0, %1;" : "=r"(u) : "f"(f));
    return u;
}
// tf32 mma: D(16x8) += A(16x8) * B(8x8), fp32 accumulate
__device__ __forceinline__ void mma_tf32(float& d0, float& d1, float& d2, float& d3,
                                         unsigned a0, unsigned a1, unsigned a2, unsigned a3,
                                         unsigned b0, unsigned b1) {
    asm volatile(
        "mma.sync.aligned.m16n8k8.row.col.f32.tf32.tf32.f32 "
        "{%0,%1,%2,%3}, {%4,%5,%6,%7}, {%8,%9}, {%0,%1,%2,%3};"
        : "+f"(d0), "+f"(d1), "+f"(d2), "+f"(d3)
        : "r"(a0), "r"(a1), "r"(a2), "r"(a3), "r"(b0), "r"(b1));
}

// ============================================================================
// Kernel 1: edge projection via tf32 mma + v4 scatter.
// 128 edges/block, 4 warps; warp w owns edges [blk*128 + 32w, +32).
//   A: warp-private smem region [32 edges][68] (tf32 bits, pad-68 ->
//      conflict-free fragment LDS: bank = 4g + tg + const).
//   mma: 2 m-tiles x 8 k-steps x 3 n-tiles = 48 HMMA per warp.
//   m-transpose: acc frags -> smem rows [32][28] OVERLAID on the warp's own
//      A region (A dead after mma; intra-warp only -> __syncwarp suffices),
//      then per-edge contiguous float4 reads -> + bias -> red.v4.
// ============================================================================
#define EPB 128

__global__ __launch_bounds__(128) void edge_kernel(
    const float* __restrict__ edge_feat,   // [E, 64]
    const float* __restrict__ W_msg,       // [64, 24]
    const float* __restrict__ b_msg,       // [24]
    const int*   __restrict__ dst_idx)     // [E]
{
    __shared__ __align__(16) unsigned As[4][32][68];   // 34816 B (tf32 bits)
    __shared__ unsigned Ws[64][24];                    // 6144 B (tf32 bits)
    __shared__ __align__(16) float Bs[24];             // bias

    const int tid = threadIdx.x;
    const int w    = tid >> 5;
    const int lane = tid & 31;
    const int g  = lane >> 2;   // 0..7
    const int tg = lane & 3;    // 0..3

    // cooperative W + bias load (tf32-convert W)
    for (int i = tid; i < EDGE_DIM * ADDED; i += 128)
        Ws[i / ADDED][i % ADDED] = cvt_tf32(W_msg[i]);
    if (tid < ADDED) Bs[tid] = b_msg[tid];

    // per-warp A load: 32 edges x 64 floats = 512 float4, contiguous in gmem
    const long long ebase = (long long)blockIdx.x * EPB + w * 32;
    {
        const float4* src = reinterpret_cast<const float4*>(edge_feat) + ebase * 16;
#pragma unroll
        for (int i = 0; i < 16; i++) {
            const int idx = i * 32 + lane;          // 0..511
            const float4 v = src[idx];
            unsigned* dst = &As[w][idx >> 4][(idx & 15) * 4];
            dst[0] = cvt_tf32(v.x);
            dst[1] = cvt_tf32(v.y);
            dst[2] = cvt_tf32(v.z);
            dst[3] = cvt_tf32(v.w);
        }
    }
    __syncthreads();   // Ws visible to all warps (A is warp-private)

    // ---- mma: m=32 (2 tiles), n=24 (3 tiles), k=64 (8 steps)
    float acc[2][3][4];
#pragma unroll
    for (int mt = 0; mt < 2; mt++)
#pragma unroll
        for (int nt = 0; nt < 3; nt++)
#pragma unroll
            for (int i = 0; i < 4; i++) acc[mt][nt][i] = 0.f;

#pragma unroll
    for (int ks = 0; ks < 8; ks++) {
        const int k0 = ks * 8;
        unsigned b0[3], b1[3];
#pragma unroll
        for (int nt = 0; nt < 3; nt++) {
            b0[nt] = Ws[k0 + tg][8 * nt + g];
            b1[nt] = Ws[k0 + tg + 4][8 * nt + g];
        }
#pragma unroll
        for (int mt = 0; mt < 2; mt++) {
            const int r = 16 * mt + g;
            const unsigned a0 = As[w][r][k0 + tg];
            const unsigned a1 = As[w][r + 8][k0 + tg];
            const unsigned a2 = As[w][r][k0 + tg + 4];
            const unsigned a3 = As[w][r + 8][k0 + tg + 4];
#pragma unroll
            for (int nt = 0; nt < 3; nt++)
                mma_tf32(acc[mt][nt][0], acc[mt][nt][1], acc[mt][nt][2], acc[mt][nt][3],
                         a0, a1, a2, a3, b0[nt], b1[nt]);
        }
    }

    // ---- transpose accs through smem (overlay on this warp's A region)
    float* msw = reinterpret_cast<float*>(&As[w][0][0]);   // [32 rows][28 floats]
    __syncwarp();
#pragma unroll
    for (int mt = 0; mt < 2; mt++) {
        const int r1 = 16 * mt + g;
        const int r2 = r1 + 8;
#pragma unroll
        for (int nt = 0; nt < 3; nt++) {
            const int c = 8 * nt + 2 * tg;
            *reinterpret_cast<float2*>(&msw[r1 * 28 + c]) =
                make_float2(acc[mt][nt][0], acc[mt][nt][1]);
            *reinterpret_cast<float2*>(&msw[r2 * 28 + c]) =
                make_float2(acc[mt][nt][2], acc[mt][nt][3]);
        }
    }
    __syncwarp();

    // ---- scatter: lane l owns edge (ebase + l); 6 red.v4 per edge
    const int d = dst_idx[ebase + lane];
    float* prow = g_ah + (long long)d * ADDED;
#pragma unroll
    for (int q = 0; q < ADDED / 4; q++) {
        const float4 v = *reinterpret_cast<const float4*>(&msw[lane * 28 + 4 * q]);
        const float4 bb = *reinterpret_cast<const float4*>(&Bs[4 * q]);
        red_add_v4(prow + 4 * q, v.x + bb.x, v.y + bb.y, v.z + bb.z, v.w + bb.w);
    }
}

// ============================================================================
// Kernel 2: node GEMM via tf32 mma.sync, full K=280 (h ++ g_ah*norm),
// bias + ReLU epilogue, g_ah re-zero. (unchanged from R4)
// ============================================================================
#define NODE_BLOCKS 782   // 782*128 = 100096 >= NN

__global__ __launch_bounds__(512, 1) void node_kernel(
    const float* __restrict__ h,      // [NN, 256]
    const float* __restrict__ norm,   // [NN, 1]
    const float* __restrict__ W1,     // [280, 256]
    const float* __restrict__ b1,     // [256]
    float* __restrict__ out)          // [NN, 256]
{
    __shared__ unsigned as_[8][136];   // A: [k][row] (transposed)
    __shared__ unsigned ws_[8][264];   // B: [k][col]

    const int tid = threadIdx.x;
    const int wid = tid >> 5;
    const int lane = tid & 31;
    const int g  = lane >> 2;
    const int tg = lane & 3;
    const int wm = wid & 3;
    const int wn = wid >> 2;
    const int row0 = blockIdx.x * 128;

    float acc[2][8][4];
#pragma unroll
    for (int mt = 0; mt < 2; mt++)
#pragma unroll
        for (int nf = 0; nf < 8; nf++)
#pragma unroll
            for (int i = 0; i < 4; i++) acc[mt][nf][i] = 0.f;

    const int br = tid >> 6;
    const int bc = (tid & 63) * 4;
    const int ar = (tid >> 1) & 127;
    const int ap = (tid & 1) * 4;

    for (int kt = 0; kt < KDIM / 8; kt++) {
        const int k0 = kt * 8;

        {
            const float4 wv = *reinterpret_cast<const float4*>(
                W1 + (long long)(k0 + br) * OUT_DIM + bc);
            uint4 u;
            u.x = cvt_tf32(wv.x); u.y = cvt_tf32(wv.y);
            u.z = cvt_tf32(wv.z); u.w = cvt_tf32(wv.w);
            *reinterpret_cast<uint4*>(&ws_[br][bc]) = u;
        }
        if (tid < 256) {
            const int grow = row0 + ar;
            float4 v = make_float4(0.f, 0.f, 0.f, 0.f);
            if (grow < NN) {
                if (k0 < H_DIM) {
                    v = *reinterpret_cast<const float4*>(
                        h + (long long)grow * H_DIM + k0 + ap);
                } else {
                    v = *reinterpret_cast<const float4*>(
                        g_ah + (long long)grow * ADDED + (k0 - H_DIM) + ap);
                    const float nr = norm[grow];
                    v.x *= nr; v.y *= nr; v.z *= nr; v.w *= nr;
                }
            }
            as_[ap + 0][ar] = cvt_tf32(v.x);
            as_[ap + 1][ar] = cvt_tf32(v.y);
            as_[ap + 2][ar] = cvt_tf32(v.z);
            as_[ap + 3][ar] = cvt_tf32(v.w);
        }
        __syncthreads();

#pragma unroll
        for (int mt = 0; mt < 2; mt++) {
            const int rb = wm * 32 + mt * 16;
            const unsigned a0 = as_[tg][rb + g];
            const unsigned a1 = as_[tg][rb + g + 8];
            const unsigned a2 = as_[tg + 4][rb + g];
            const unsigned a3 = as_[tg + 4][rb + g + 8];
#pragma unroll
            for (int nf = 0; nf < 8; nf++) {
                const int cb = wn * 64 + nf * 8;
                const unsigned b0 = ws_[tg][cb + g];
                const unsigned b1v = ws_[tg + 4][cb + g];
                mma_tf32(acc[mt][nf][0], acc[mt][nf][1], acc[mt][nf][2], acc[mt][nf][3],
                         a0, a1, a2, a3, b0, b1v);
            }
        }
        __syncthreads();
    }

    {
        const int nf4 = 128 * (ADDED / 4);
        for (int i = tid; i < nf4; i += 512) {
            const int grow = row0 + i / (ADDED / 4);
            if (grow < NN)
                reinterpret_cast<float4*>(g_ah)[(long long)grow * (ADDED / 4)
                                                + (i % (ADDED / 4))] =
                    make_float4(0.f, 0.f, 0.f, 0.f);
        }
    }

#pragma unroll
    for (int nf = 0; nf < 8; nf++) {
        const int col = wn * 64 + nf * 8 + 2 * tg;
        const float2 bb = *reinterpret_cast<const float2*>(b1 + col);
#pragma unroll
        for (int mt = 0; mt < 2; mt++) {
            const int r = row0 + wm * 32 + mt * 16 + g;
            if (r < NN) {
                float2 o;
                o.x = fmaxf(acc[mt][nf][0] + bb.x, 0.f);
                o.y = fmaxf(acc[mt][nf][1] + bb.y, 0.f);
                *reinterpret_cast<float2*>(out + (long long)r * OUT_DIM + col) = o;
            }
            const int r2 = r + 8;
            if (r2 < NN) {
                float2 o;
                o.x = fmaxf(acc[mt][nf][2] + bb.x, 0.f);
                o.y = fmaxf(acc[mt][nf][3] + bb.y, 0.f);
                *reinterpret_cast<float2*>(out + (long long)r2 * OUT_DIM + col) = o;
            }
        }
    }
}

// ---------------- launch ----------------
extern "C" void kernel_launch(void* const* d_in, const int* in_sizes, int n_in,
                              void* d_out, int out_size) {
    const float* h         = (const float*)d_in[0];
    const float* edge_feat = (const float*)d_in[1];
    const float* norm      = (const float*)d_in[2];
    const float* W_msg     = (const float*)d_in[3];
    const float* b_msg     = (const float*)d_in[4];
    const float* W1        = (const float*)d_in[5];
    const float* b1        = (const float*)d_in[6];
    const int*   dst_idx   = (const int*)d_in[7];
    float* out = (float*)d_out;

    // 1. edge projection (tf32 mma) + v4 scatter
    edge_kernel<<<E_TOTAL / EPB, 128>>>(edge_feat, W_msg, b_msg, dst_idx);

    // 2. node GEMM (tf32 tensor cores, full K=280) + bias + ReLU + g_ah re-zero
    node_kernel<<<NODE_BLOCKS, 512>>>(h, norm, W1, b1, out);
}

// round 6
// speedup vs baseline: 1.7690x; 1.2354x over previous
#include <cuda_runtime.h>
#include <cuda_bf16.h>

// Problem constants (fixed shapes per reference)
#define E_TOTAL   3200000
#define NN        100000
#define EDGE_DIM  64
#define ADDED     24
#define H_DIM     256
#define KDIM      280
#define OUT_DIM   256

// Scatter-sum scratch: [NN, ADDED] fp32 = 9.6 MB.
// Zero-initialized at module load; node_kernel re-zeroes rows after consuming
// them, preserving the invariant across graph replays.
__device__ float g_ah[NN * ADDED];

// ---------------- helpers ----------------
__device__ __forceinline__ void red_add_v4(float* p, float a, float b, float c, float d) {
    asm volatile("red.global.add.v4.f32 [%0], {%1, %2, %3, %4};"
                 :: "l"(p), "f"(a), "f"(b), "f"(c), "f"(d) : "memory");
}
__device__ __forceinline__ unsigned cvt_tf32(float f) {
    unsigned u;
    asm("cvt.rna.tf32.f32 %0, %1;" : "=r"(u) : "f"(f));
    return u;
}
__device__ __forceinline__ void mma_tf32(float& d0, float& d1, float& d2, float& d3,
                                         unsigned a0, unsigned a1, unsigned a2, unsigned a3,
                                         unsigned b0, unsigned b1) {
    asm volatile(
        "mma.sync.aligned.m16n8k8.row.col.f32.tf32.tf32.f32 "
        "{%0,%1,%2,%3}, {%4,%5,%6,%7}, {%8,%9}, {%0,%1,%2,%3};"
        : "+f"(d0), "+f"(d1), "+f"(d2), "+f"(d3)
        : "r"(a0), "r"(a1), "r"(a2), "r"(a3), "r"(b0), "r"(b1));
}

// ============================================================================
// Kernel 1: edge projection via tf32 mma + v4 scatter. (unchanged from R5)
// ============================================================================
#define EPB 128

__global__ __launch_bounds__(128) void edge_kernel(
    const float* __restrict__ edge_feat,   // [E, 64]
    const float* __restrict__ W_msg,       // [64, 24]
    const float* __restrict__ b_msg,       // [24]
    const int*   __restrict__ dst_idx)     // [E]
{
    __shared__ __align__(16) unsigned As[4][32][68];
    __shared__ unsigned Ws[64][24];
    __shared__ __align__(16) float Bs[24];

    const int tid = threadIdx.x;
    const int w    = tid >> 5;
    const int lane = tid & 31;
    const int g  = lane >> 2;
    const int tg = lane & 3;

    for (int i = tid; i < EDGE_DIM * ADDED; i += 128)
        Ws[i / ADDED][i % ADDED] = cvt_tf32(W_msg[i]);
    if (tid < ADDED) Bs[tid] = b_msg[tid];

    const long long ebase = (long long)blockIdx.x * EPB + w * 32;
    {
        const float4* src = reinterpret_cast<const float4*>(edge_feat) + ebase * 16;
#pragma unroll
        for (int i = 0; i < 16; i++) {
            const int idx = i * 32 + lane;
            const float4 v = src[idx];
            unsigned* dst = &As[w][idx >> 4][(idx & 15) * 4];
            dst[0] = cvt_tf32(v.x);
            dst[1] = cvt_tf32(v.y);
            dst[2] = cvt_tf32(v.z);
            dst[3] = cvt_tf32(v.w);
        }
    }
    __syncthreads();

    float acc[2][3][4];
#pragma unroll
    for (int mt = 0; mt < 2; mt++)
#pragma unroll
        for (int nt = 0; nt < 3; nt++)
#pragma unroll
            for (int i = 0; i < 4; i++) acc[mt][nt][i] = 0.f;

#pragma unroll
    for (int ks = 0; ks < 8; ks++) {
        const int k0 = ks * 8;
        unsigned b0[3], b1[3];
#pragma unroll
        for (int nt = 0; nt < 3; nt++) {
            b0[nt] = Ws[k0 + tg][8 * nt + g];
            b1[nt] = Ws[k0 + tg + 4][8 * nt + g];
        }
#pragma unroll
        for (int mt = 0; mt < 2; mt++) {
            const int r = 16 * mt + g;
            const unsigned a0 = As[w][r][k0 + tg];
            const unsigned a1 = As[w][r + 8][k0 + tg];
            const unsigned a2 = As[w][r][k0 + tg + 4];
            const unsigned a3 = As[w][r + 8][k0 + tg + 4];
#pragma unroll
            for (int nt = 0; nt < 3; nt++)
                mma_tf32(acc[mt][nt][0], acc[mt][nt][1], acc[mt][nt][2], acc[mt][nt][3],
                         a0, a1, a2, a3, b0[nt], b1[nt]);
        }
    }

    float* msw = reinterpret_cast<float*>(&As[w][0][0]);
    __syncwarp();
#pragma unroll
    for (int mt = 0; mt < 2; mt++) {
        const int r1 = 16 * mt + g;
        const int r2 = r1 + 8;
#pragma unroll
        for (int nt = 0; nt < 3; nt++) {
            const int c = 8 * nt + 2 * tg;
            *reinterpret_cast<float2*>(&msw[r1 * 28 + c]) =
                make_float2(acc[mt][nt][0], acc[mt][nt][1]);
            *reinterpret_cast<float2*>(&msw[r2 * 28 + c]) =
                make_float2(acc[mt][nt][2], acc[mt][nt][3]);
        }
    }
    __syncwarp();

    const int d = dst_idx[ebase + lane];
    float* prow = g_ah + (long long)d * ADDED;
#pragma unroll
    for (int q = 0; q < ADDED / 4; q++) {
        const float4 v = *reinterpret_cast<const float4*>(&msw[lane * 28 + 4 * q]);
        const float4 bb = *reinterpret_cast<const float4*>(&Bs[4 * q]);
        red_add_v4(prow + 4 * q, v.x + bb.x, v.y + bb.y, v.z + bb.z, v.w + bb.w);
    }
}

// ============================================================================
// Kernel 2: node GEMM, tf32 mma, SOFTWARE-PIPELINED.
// Block = 128 rows x 256 cols, 512 threads = 16 warps (4m x 4n; warp 32x64).
// K-tile = 16, 18 tiles covering zero-padded K=288 (real K=280).
// Register-staged pipeline: LDG(kt+1) issued before mma(kt); single smem
// buffer with two barriers per iteration.
// ============================================================================
#define NODE_BLOCKS 782   // 782*128 = 100096 >= NN
#define NKT 18            // k-tiles of 16 over 288

__global__ __launch_bounds__(512, 1) void node_kernel(
    const float* __restrict__ h,      // [NN, 256]
    const float* __restrict__ norm,   // [NN, 1]
    const float* __restrict__ W1,     // [280, 256]
    const float* __restrict__ b1,     // [256]
    float* __restrict__ out)          // [NN, 256]
{
    __shared__ __align__(16) unsigned As[128][20];    // [row][k] tf32, pad 20
    __shared__ __align__(16) unsigned Ws[16][264];    // [k][col] tf32, pad 264

    const int tid = threadIdx.x;
    const int wid = tid >> 5;
    const int lane = tid & 31;
    const int g  = lane >> 2;
    const int tg = lane & 3;
    const int wm = wid & 3;          // rows wm*32..+31
    const int wn = wid >> 2;         // cols wn*64..+63
    const int row0 = blockIdx.x * 128;

    // loader roles (fixed across iterations)
    const int arow = tid >> 2;             // A: row 0..127
    const int akq  = (tid & 3) * 4;        // A: k quad offset 0,4,8,12
    const int brow = tid >> 6;             // B: k row (tid>>6 twice: +0, +8... see below)
    const int bc4  = (tid & 63) * 4;       // B: col 0..252

    const int agrow = row0 + arow;
    const bool arv = (agrow < NN);
    const float nr = arv ? norm[agrow] : 0.f;   // only used for tail tiles

    float acc[2][8][4];
#pragma unroll
    for (int mt = 0; mt < 2; mt++)
#pragma unroll
        for (int nf = 0; nf < 8; nf++)
#pragma unroll
            for (int i = 0; i < 4; i++) acc[mt][nf][i] = 0.f;

    float4 av, bv0, bv1;

    // ---- tile loader into registers (no smem writes)
    auto load_tile = [&](int kt) {
        const int k0 = kt * 16;
        // A: row agrow, k = k0 + akq .. +3
        {
            const int ka = k0 + akq;
            av = make_float4(0.f, 0.f, 0.f, 0.f);
            if (arv) {
                if (ka < H_DIM) {
                    av = *reinterpret_cast<const float4*>(
                        h + (long long)agrow * H_DIM + ka);
                } else if (ka - H_DIM < ADDED) {
                    av = *reinterpret_cast<const float4*>(
                        g_ah + (long long)agrow * ADDED + (ka - H_DIM));
                    av.x *= nr; av.y *= nr; av.z *= nr; av.w *= nr;
                }
            }
        }
        // B: two rows (brow, brow+8), col bc4..+3
        {
            const int kb0 = k0 + brow;
            const int kb1 = k0 + brow + 8;
            bv0 = make_float4(0.f, 0.f, 0.f, 0.f);
            bv1 = make_float4(0.f, 0.f, 0.f, 0.f);
            if (kb0 < KDIM)
                bv0 = *reinterpret_cast<const float4*>(
                    W1 + (long long)kb0 * OUT_DIM + bc4);
            if (kb1 < KDIM)
                bv1 = *reinterpret_cast<const float4*>(
                    W1 + (long long)kb1 * OUT_DIM + bc4);
        }
    };

    load_tile(0);

    for (int kt = 0; kt < NKT; kt++) {
        // ---- commit staged tile to smem (cvt to tf32 on the way)
        {
            unsigned* ad = &As[arow][akq];
            ad[0] = cvt_tf32(av.x); ad[1] = cvt_tf32(av.y);
            ad[2] = cvt_tf32(av.z); ad[3] = cvt_tf32(av.w);
            unsigned* bd0 = &Ws[brow][bc4];
            bd0[0] = cvt_tf32(bv0.x); bd0[1] = cvt_tf32(bv0.y);
            bd0[2] = cvt_tf32(bv0.z); bd0[3] = cvt_tf32(bv0.w);
            unsigned* bd1 = &Ws[brow + 8][bc4];
            bd1[0] = cvt_tf32(bv1.x); bd1[1] = cvt_tf32(bv1.y);
            bd1[2] = cvt_tf32(bv1.z); bd1[3] = cvt_tf32(bv1.w);
        }
        __syncthreads();

        // ---- issue next tile's LDGs (latency hides under mma below)
        if (kt + 1 < NKT) load_tile(kt + 1);

        // ---- mma on current smem tile: 2 k-steps x 2 m-tiles x 8 n-frags
#pragma unroll
        for (int ks = 0; ks < 2; ks++) {
            const int kk = ks * 8;
#pragma unroll
            for (int mt = 0; mt < 2; mt++) {
                const int rb = wm * 32 + mt * 16;
                const unsigned a0 = As[rb + g][kk + tg];
                const unsigned a1 = As[rb + g + 8][kk + tg];
                const unsigned a2 = As[rb + g][kk + tg + 4];
                const unsigned a3 = As[rb + g + 8][kk + tg + 4];
#pragma unroll
                for (int nf = 0; nf < 8; nf++) {
                    const int cb = wn * 64 + nf * 8;
                    const unsigned b0 = Ws[kk + tg][cb + g];
                    const unsigned b1v = Ws[kk + tg + 4][cb + g];
                    mma_tf32(acc[mt][nf][0], acc[mt][nf][1],
                             acc[mt][nf][2], acc[mt][nf][3],
                             a0, a1, a2, a3, b0, b1v);
                }
            }
        }
        __syncthreads();   // smem safe to overwrite next iteration
    }

    // ---- re-zero this block's g_ah rows (all reads completed above)
    {
        const int nf4 = 128 * (ADDED / 4);
        for (int i = tid; i < nf4; i += 512) {
            const int grow = row0 + i / (ADDED / 4);
            if (grow < NN)
                reinterpret_cast<float4*>(g_ah)[(long long)grow * (ADDED / 4)
                                                + (i % (ADDED / 4))] =
                    make_float4(0.f, 0.f, 0.f, 0.f);
        }
    }

    // ---- epilogue: bias + relu + store
#pragma unroll
    for (int nf = 0; nf < 8; nf++) {
        const int col = wn * 64 + nf * 8 + 2 * tg;
        const float2 bb = *reinterpret_cast<const float2*>(b1 + col);
#pragma unroll
        for (int mt = 0; mt < 2; mt++) {
            const int r = row0 + wm * 32 + mt * 16 + g;
            if (r < NN) {
                float2 o;
                o.x = fmaxf(acc[mt][nf][0] + bb.x, 0.f);
                o.y = fmaxf(acc[mt][nf][1] + bb.y, 0.f);
                *reinterpret_cast<float2*>(out + (long long)r * OUT_DIM + col) = o;
            }
            const int r2 = r + 8;
            if (r2 < NN) {
                float2 o;
                o.x = fmaxf(acc[mt][nf][2] + bb.x, 0.f);
                o.y = fmaxf(acc[mt][nf][3] + bb.y, 0.f);
                *reinterpret_cast<float2*>(out + (long long)r2 * OUT_DIM + col) = o;
            }
        }
    }
}

// ---------------- launch ----------------
extern "C" void kernel_launch(void* const* d_in, const int* in_sizes, int n_in,
                              void* d_out, int out_size) {
    const float* h         = (const float*)d_in[0];
    const float* edge_feat = (const float*)d_in[1];
    const float* norm      = (const float*)d_in[2];
    const float* W_msg     = (const float*)d_in[3];
    const float* b_msg     = (const float*)d_in[4];
    const float* W1        = (const float*)d_in[5];
    const float* b1        = (const float*)d_in[6];
    const int*   dst_idx   = (const int*)d_in[7];
    float* out = (float*)d_out;

    // 1. edge projection (tf32 mma) + v4 scatter
    edge_kernel<<<E_TOTAL / EPB, 128>>>(edge_feat, W_msg, b_msg, dst_idx);

    // 2. node GEMM (pipelined tf32 tensor cores) + bias + ReLU + g_ah re-zero
    node_kernel<<<NODE_BLOCKS, 512>>>(h, norm, W1, b1, out);
}

// round 7
// speedup vs baseline: 1.8190x; 1.0283x over previous
#include <cuda_runtime.h>
#include <cuda_bf16.h>

// Problem constants (fixed shapes per reference)
#define E_TOTAL   3200000
#define NN        100000
#define EDGE_DIM  64
#define ADDED     24
#define H_DIM     256
#define KDIM      280
#define OUT_DIM   256

// Scatter-sum scratch: [NN, ADDED] fp32 = 9.6 MB. Zeroed by zero_kernel at the
// start of every call (zero-before-use), so no cross-call invariant needed.
__device__ float g_ah[NN * ADDED];

// ---------------- helpers ----------------
__device__ __forceinline__ void red_add_v4(float* p, float a, float b, float c, float d) {
    asm volatile("red.global.add.v4.f32 [%0], {%1, %2, %3, %4};"
                 :: "l"(p), "f"(a), "f"(b), "f"(c), "f"(d) : "memory");
}
__device__ __forceinline__ unsigned cvt_tf32(float f) {
    unsigned u;
    asm("cvt.rna.tf32.f32 %0, %1;" : "=r"(u) : "f"(f));
    return u;
}
__device__ __forceinline__ void mma_tf32(float& d0, float& d1, float& d2, float& d3,
                                         unsigned a0, unsigned a1, unsigned a2, unsigned a3,
                                         unsigned b0, unsigned b1) {
    asm volatile(
        "mma.sync.aligned.m16n8k8.row.col.f32.tf32.tf32.f32 "
        "{%0,%1,%2,%3}, {%4,%5,%6,%7}, {%8,%9}, {%0,%1,%2,%3};"
        : "+f"(d0), "+f"(d1), "+f"(d2), "+f"(d3)
        : "r"(a0), "r"(a1), "r"(a2), "r"(a3), "r"(b0), "r"(b1));
}

// ============================================================================
// Kernel 0: zero the scatter buffer (runs before edge_kernel every call)
// ============================================================================
__global__ void zero_kernel() {
    int i = blockIdx.x * blockDim.x + threadIdx.x;
    const int n4 = NN * ADDED / 4;  // 600000
    if (i < n4)
        reinterpret_cast<float4*>(g_ah)[i] = make_float4(0.f, 0.f, 0.f, 0.f);
}

// ============================================================================
// Kernel 1: edge projection via tf32 mma + v4 scatter. (unchanged from R5)
// ============================================================================
#define EPB 128

__global__ __launch_bounds__(128) void edge_kernel(
    const float* __restrict__ edge_feat,   // [E, 64]
    const float* __restrict__ W_msg,       // [64, 24]
    const float* __restrict__ b_msg,       // [24]
    const int*   __restrict__ dst_idx)     // [E]
{
    __shared__ __align__(16) unsigned As[4][32][68];
    __shared__ unsigned Ws[64][24];
    __shared__ __align__(16) float Bs[24];

    const int tid = threadIdx.x;
    const int w    = tid >> 5;
    const int lane = tid & 31;
    const int g  = lane >> 2;
    const int tg = lane & 3;

    for (int i = tid; i < EDGE_DIM * ADDED; i += 128)
        Ws[i / ADDED][i % ADDED] = cvt_tf32(W_msg[i]);
    if (tid < ADDED) Bs[tid] = b_msg[tid];

    const long long ebase = (long long)blockIdx.x * EPB + w * 32;
    {
        const float4* src = reinterpret_cast<const float4*>(edge_feat) + ebase * 16;
#pragma unroll
        for (int i = 0; i < 16; i++) {
            const int idx = i * 32 + lane;
            const float4 v = src[idx];
            unsigned* dst = &As[w][idx >> 4][(idx & 15) * 4];
            dst[0] = cvt_tf32(v.x);
            dst[1] = cvt_tf32(v.y);
            dst[2] = cvt_tf32(v.z);
            dst[3] = cvt_tf32(v.w);
        }
    }
    __syncthreads();

    float acc[2][3][4];
#pragma unroll
    for (int mt = 0; mt < 2; mt++)
#pragma unroll
        for (int nt = 0; nt < 3; nt++)
#pragma unroll
            for (int i = 0; i < 4; i++) acc[mt][nt][i] = 0.f;

#pragma unroll
    for (int ks = 0; ks < 8; ks++) {
        const int k0 = ks * 8;
        unsigned b0[3], b1[3];
#pragma unroll
        for (int nt = 0; nt < 3; nt++) {
            b0[nt] = Ws[k0 + tg][8 * nt + g];
            b1[nt] = Ws[k0 + tg + 4][8 * nt + g];
        }
#pragma unroll
        for (int mt = 0; mt < 2; mt++) {
            const int r = 16 * mt + g;
            const unsigned a0 = As[w][r][k0 + tg];
            const unsigned a1 = As[w][r + 8][k0 + tg];
            const unsigned a2 = As[w][r][k0 + tg + 4];
            const unsigned a3 = As[w][r + 8][k0 + tg + 4];
#pragma unroll
            for (int nt = 0; nt < 3; nt++)
                mma_tf32(acc[mt][nt][0], acc[mt][nt][1], acc[mt][nt][2], acc[mt][nt][3],
                         a0, a1, a2, a3, b0[nt], b1[nt]);
        }
    }

    float* msw = reinterpret_cast<float*>(&As[w][0][0]);
    __syncwarp();
#pragma unroll
    for (int mt = 0; mt < 2; mt++) {
        const int r1 = 16 * mt + g;
        const int r2 = r1 + 8;
#pragma unroll
        for (int nt = 0; nt < 3; nt++) {
            const int c = 8 * nt + 2 * tg;
            *reinterpret_cast<float2*>(&msw[r1 * 28 + c]) =
                make_float2(acc[mt][nt][0], acc[mt][nt][1]);
            *reinterpret_cast<float2*>(&msw[r2 * 28 + c]) =
                make_float2(acc[mt][nt][2], acc[mt][nt][3]);
        }
    }
    __syncwarp();

    const int d = dst_idx[ebase + lane];
    float* prow = g_ah + (long long)d * ADDED;
#pragma unroll
    for (int q = 0; q < ADDED / 4; q++) {
        const float4 v = *reinterpret_cast<const float4*>(&msw[lane * 28 + 4 * q]);
        const float4 bb = *reinterpret_cast<const float4*>(&Bs[4 * q]);
        red_add_v4(prow + 4 * q, v.x + bb.x, v.y + bb.y, v.z + bb.z, v.w + bb.w);
    }
}

// ============================================================================
// Kernel 2: node GEMM, tf32 mma, double-buffered pipeline.
// Block = 128 rows x 128 cols, 256 threads = 8 warps (4m x 2n; warp 32x64).
// Grid = 782 row-tiles x 2 col-tiles. 2 CTAs/SM. One barrier per k-tile.
// ============================================================================
#define ROW_TILES 782     // 782*128 = 100096 >= NN
#define NKT 18            // k-tiles of 16 over zero-padded 288

__global__ __launch_bounds__(256, 2) void node_kernel(
    const float* __restrict__ h,      // [NN, 256]
    const float* __restrict__ norm,   // [NN, 1]
    const float* __restrict__ W1,     // [280, 256]
    const float* __restrict__ b1,     // [256]
    float* __restrict__ out)          // [NN, 256]
{
    __shared__ __align__(16) unsigned As[2][128][20];   // [buf][row][k] 20480 B
    __shared__ __align__(16) unsigned Ws[2][16][136];   // [buf][k][col] 17408 B

    const int tid = threadIdx.x;
    const int wid = tid >> 5;        // 0..7
    const int lane = tid & 31;
    const int g  = lane >> 2;
    const int tg = lane & 3;
    const int wm = wid & 3;          // rows wm*32..+31
    const int wn = wid >> 2;         // cols wn*64..+63 (within 128-col tile)
    const int rt = blockIdx.x >> 1;
    const int cb = blockIdx.x & 1;
    const int row0 = rt * 128;
    const int col0 = cb * 128;

    // loader roles
    const int arow = tid >> 1;            // A: row 0..127
    const int aq   = (tid & 1) * 8;       // A: k offset 0 or 8 (2 quads each)
    const int brow = tid >> 4;            // B: k row 0..15
    const int bcol = (tid & 15) * 4;      // B: col 0..60 (second quad at +64)

    const int agrow = row0 + arow;
    const bool arv = (agrow < NN);
    const float nr = arv ? norm[agrow] : 0.f;

    float acc[2][8][4];
#pragma unroll
    for (int mt = 0; mt < 2; mt++)
#pragma unroll
        for (int nf = 0; nf < 8; nf++)
#pragma unroll
            for (int i = 0; i < 4; i++) acc[mt][nf][i] = 0.f;

    float4 av[2], bv[2];

    auto fetchA = [&](int ka) -> float4 {
        float4 v = make_float4(0.f, 0.f, 0.f, 0.f);
        if (arv) {
            if (ka < H_DIM) {
                v = *reinterpret_cast<const float4*>(h + (long long)agrow * H_DIM + ka);
            } else if (ka < KDIM) {
                v = *reinterpret_cast<const float4*>(
                    g_ah + (long long)agrow * ADDED + (ka - H_DIM));
                v.x *= nr; v.y *= nr; v.z *= nr; v.w *= nr;
            }
        }
        return v;
    };

    auto load_tile = [&](int kt) {
        const int k0 = kt * 16;
        av[0] = fetchA(k0 + aq);
        av[1] = fetchA(k0 + aq + 4);
        const int kb = k0 + brow;
        bv[0] = make_float4(0.f, 0.f, 0.f, 0.f);
        bv[1] = make_float4(0.f, 0.f, 0.f, 0.f);
        if (kb < KDIM) {
            bv[0] = *reinterpret_cast<const float4*>(
                W1 + (long long)kb * OUT_DIM + col0 + bcol);
            bv[1] = *reinterpret_cast<const float4*>(
                W1 + (long long)kb * OUT_DIM + col0 + bcol + 64);
        }
    };

    auto cvt_sts = [&](int buf) {
        unsigned* ad = &As[buf][arow][aq];
        ad[0] = cvt_tf32(av[0].x); ad[1] = cvt_tf32(av[0].y);
        ad[2] = cvt_tf32(av[0].z); ad[3] = cvt_tf32(av[0].w);
        ad[4] = cvt_tf32(av[1].x); ad[5] = cvt_tf32(av[1].y);
        ad[6] = cvt_tf32(av[1].z); ad[7] = cvt_tf32(av[1].w);
        unsigned* bd0 = &Ws[buf][brow][bcol];
        bd0[0] = cvt_tf32(bv[0].x); bd0[1] = cvt_tf32(bv[0].y);
        bd0[2] = cvt_tf32(bv[0].z); bd0[3] = cvt_tf32(bv[0].w);
        unsigned* bd1 = &Ws[buf][brow][bcol + 64];
        bd1[0] = cvt_tf32(bv[1].x); bd1[1] = cvt_tf32(bv[1].y);
        bd1[2] = cvt_tf32(bv[1].z); bd1[3] = cvt_tf32(bv[1].w);
    };

    load_tile(0);
    cvt_sts(0);
    __syncthreads();

    for (int kt = 0; kt < NKT; kt++) {
        const int buf = kt & 1;
        if (kt + 1 < NKT) load_tile(kt + 1);   // LDG issue (latency under mma)

        // mma on current buffer: 2 k-steps x 2 m-tiles x 8 n-frags
#pragma unroll
        for (int ks = 0; ks < 2; ks++) {
            const int kk = ks * 8;
#pragma unroll
            for (int mt = 0; mt < 2; mt++) {
                const int rb = wm * 32 + mt * 16;
                const unsigned a0 = As[buf][rb + g][kk + tg];
                const unsigned a1 = As[buf][rb + g + 8][kk + tg];
                const unsigned a2 = As[buf][rb + g][kk + tg + 4];
                const unsigned a3 = As[buf][rb + g + 8][kk + tg + 4];
#pragma unroll
                for (int nf = 0; nf < 8; nf++) {
                    const int cc = wn * 64 + nf * 8;
                    const unsigned b0 = Ws[buf][kk + tg][cc + g];
                    const unsigned b1v = Ws[buf][kk + tg + 4][cc + g];
                    mma_tf32(acc[mt][nf][0], acc[mt][nf][1],
                             acc[mt][nf][2], acc[mt][nf][3],
                             a0, a1, a2, a3, b0, b1v);
                }
            }
        }

        if (kt + 1 < NKT) cvt_sts((kt + 1) & 1);   // write other buffer
        __syncthreads();
    }

    // epilogue: bias + relu + store
#pragma unroll
    for (int nf = 0; nf < 8; nf++) {
        const int col = col0 + wn * 64 + nf * 8 + 2 * tg;
        const float2 bb = *reinterpret_cast<const float2*>(b1 + col);
#pragma unroll
        for (int mt = 0; mt < 2; mt++) {
            const int r = row0 + wm * 32 + mt * 16 + g;
            if (r < NN) {
                float2 o;
                o.x = fmaxf(acc[mt][nf][0] + bb.x, 0.f);
                o.y = fmaxf(acc[mt][nf][1] + bb.y, 0.f);
                *reinterpret_cast<float2*>(out + (long long)r * OUT_DIM + col) = o;
            }
            const int r2 = r + 8;
            if (r2 < NN) {
                float2 o;
                o.x = fmaxf(acc[mt][nf][2] + bb.x, 0.f);
                o.y = fmaxf(acc[mt][nf][3] + bb.y, 0.f);
                *reinterpret_cast<float2*>(out + (long long)r2 * OUT_DIM + col) = o;
            }
        }
    }
}

// ---------------- launch ----------------
extern "C" void kernel_launch(void* const* d_in, const int* in_sizes, int n_in,
                              void* d_out, int out_size) {
    const float* h         = (const float*)d_in[0];
    const float* edge_feat = (const float*)d_in[1];
    const float* norm      = (const float*)d_in[2];
    const float* W_msg     = (const float*)d_in[3];
    const float* b_msg     = (const float*)d_in[4];
    const float* W1        = (const float*)d_in[5];
    const float* b1        = (const float*)d_in[6];
    const int*   dst_idx   = (const int*)d_in[7];
    float* out = (float*)d_out;

    // 0. zero scatter buffer (zero-before-use)
    zero_kernel<<<(NN * ADDED / 4 + 255) / 256, 256>>>();

    // 1. edge projection (tf32 mma) + v4 scatter
    edge_kernel<<<E_TOTAL / EPB, 128>>>(edge_feat, W_msg, b_msg, dst_idx);

    // 2. node GEMM (double-buffered tf32 tensor cores) + bias + ReLU
    node_kernel<<<ROW_TILES * 2, 256>>>(h, norm, W1, b1, out);
}

// round 8
// speedup vs baseline: 2.1742x; 1.1953x over previous
#include <cuda_runtime.h>
#include <cuda_bf16.h>

// Problem constants (fixed shapes per reference)
#define E_TOTAL   3200000
#define NN        100000
#define EDGE_DIM  64
#define ADDED     24
#define H_DIM     256
#define KDIM      280
#define OUT_DIM   256

#define NBLK      391      // ceil(NN/256) for scans

// ---- scratch (device globals; no runtime allocation) ----
__device__ unsigned g_deg[NN];          // in-degree
__device__ unsigned g_bsum[512];        // per-scan-block sums (>= NBLK)
__device__ unsigned g_off[NN];          // CSR start offsets
__device__ unsigned g_cursor[NN];       // fill cursors
__device__ int      g_eid[E_TOTAL];     // CSR edge ids
__device__ float    g_S[NN * EDGE_DIM]; // per-node summed edge features (25.6 MB)
__device__ float    g_B2[65 * 256];     // rows 0..63: W_msg@W1b ; row 64: b_msg@W1b

// ---------------- helpers ----------------
__device__ __forceinline__ unsigned cvt_tf32(float f) {
    unsigned u;
    asm("cvt.rna.tf32.f32 %0, %1;" : "=r"(u) : "f"(f));
    return u;
}
__device__ __forceinline__ void mma_tf32(float& d0, float& d1, float& d2, float& d3,
                                         unsigned a0, unsigned a1, unsigned a2, unsigned a3,
                                         unsigned b0, unsigned b1) {
    asm volatile(
        "mma.sync.aligned.m16n8k8.row.col.f32.tf32.tf32.f32 "
        "{%0,%1,%2,%3}, {%4,%5,%6,%7}, {%8,%9}, {%0,%1,%2,%3};"
        : "+f"(d0), "+f"(d1), "+f"(d2), "+f"(d3)
        : "r"(a0), "r"(a1), "r"(a2), "r"(a3), "r"(b0), "r"(b1));
}

// ============================================================================
// CSR build
// ============================================================================
__global__ void zero_deg_kernel() {
    int i = blockIdx.x * blockDim.x + threadIdx.x;
    if (i < NN) g_deg[i] = 0u;
}

__global__ void hist_kernel(const int* __restrict__ dst_idx) {
    int e = blockIdx.x * blockDim.x + threadIdx.x;
    if (e < E_TOTAL) atomicAdd(&g_deg[dst_idx[e]], 1u);
}

// per-block degree sums
__global__ void scan1_kernel() {
    __shared__ unsigned s[256];
    const int t = threadIdx.x;
    const int n = blockIdx.x * 256 + t;
    s[t] = (n < NN) ? g_deg[n] : 0u;
    __syncthreads();
#pragma unroll
    for (int d = 128; d > 0; d >>= 1) {
        if (t < d) s[t] += s[t + d];
        __syncthreads();
    }
    if (t == 0) g_bsum[blockIdx.x] = s[0];
}

// exclusive scan of block sums (single block)
__global__ void scan2_kernel() {
    __shared__ unsigned s[512];
    const int t = threadIdx.x;
    s[t] = (t < NBLK) ? g_bsum[t] : 0u;
    __syncthreads();
#pragma unroll
    for (int d = 1; d < 512; d <<= 1) {
        unsigned v = (t >= d) ? s[t - d] : 0u;
        __syncthreads();
        s[t] += v;
        __syncthreads();
    }
    if (t < NBLK) g_bsum[t] = (t == 0) ? 0u : s[t - 1];
}

// per-element exclusive offsets = blockBase + local exclusive scan
__global__ void scan3_kernel() {
    __shared__ unsigned s[256];
    const int t = threadIdx.x;
    const int n = blockIdx.x * 256 + t;
    const unsigned d = (n < NN) ? g_deg[n] : 0u;
    s[t] = d;
    __syncthreads();
#pragma unroll
    for (int dd = 1; dd < 256; dd <<= 1) {
        unsigned v = (t >= dd) ? s[t - dd] : 0u;
        __syncthreads();
        s[t] += v;
        __syncthreads();
    }
    if (n < NN) {
        const unsigned off = g_bsum[blockIdx.x] + s[t] - d;   // exclusive
        g_off[n] = off;
        g_cursor[n] = off;
    }
}

__global__ void fill_kernel(const int* __restrict__ dst_idx) {
    int e = blockIdx.x * blockDim.x + threadIdx.x;
    if (e < E_TOTAL) {
        const unsigned pos = atomicAdd(&g_cursor[dst_idx[e]], 1u);
        g_eid[pos] = e;
    }
}

// ============================================================================
// Gather: S[n] = sum of edge_feat rows of node n's incoming edges (no atomics)
// One warp per node; two half-warps process 2 edges/iter; lane owns 4 dims.
// ============================================================================
__global__ __launch_bounds__(256) void gather_kernel(
    const float* __restrict__ edge_feat)   // [E, 64]
{
    const int tid = threadIdx.x;
    const int warp = tid >> 5;
    const int lane = tid & 31;
    const int hw  = lane >> 4;     // half-warp 0/1
    const int l16 = lane & 15;     // lane in half-warp -> dims 4*l16..+3

    const int n = blockIdx.x * 8 + warp;
    if (n >= NN) return;

    const unsigned off = g_off[n];
    const unsigned deg = g_deg[n];

    float4 acc = make_float4(0.f, 0.f, 0.f, 0.f);
    unsigned i = hw;
    // unrolled-by-2 (per half-warp) main loop for MLP
    for (; i + 2 < deg; i += 4) {
        const int e0 = g_eid[off + i];
        const int e1 = g_eid[off + i + 2];
        const float4 v0 = *reinterpret_cast<const float4*>(
            edge_feat + (long long)e0 * EDGE_DIM + 4 * l16);
        const float4 v1 = *reinterpret_cast<const float4*>(
            edge_feat + (long long)e1 * EDGE_DIM + 4 * l16);
        acc.x += v0.x + v1.x; acc.y += v0.y + v1.y;
        acc.z += v0.z + v1.z; acc.w += v0.w + v1.w;
    }
    for (; i < deg; i += 2) {
        const int e = g_eid[off + i];
        const float4 v = *reinterpret_cast<const float4*>(
            edge_feat + (long long)e * EDGE_DIM + 4 * l16);
        acc.x += v.x; acc.y += v.y; acc.z += v.z; acc.w += v.w;
    }
    // combine the two half-warps (same dims, different edge subsets)
    acc.x += __shfl_xor_sync(0xffffffffu, acc.x, 16);
    acc.y += __shfl_xor_sync(0xffffffffu, acc.y, 16);
    acc.z += __shfl_xor_sync(0xffffffffu, acc.z, 16);
    acc.w += __shfl_xor_sync(0xffffffffu, acc.w, 16);
    if (hw == 0)
        *reinterpret_cast<float4*>(g_S + (long long)n * EDGE_DIM + 4 * l16) = acc;
}

// ============================================================================
// W2 precompute: B2[0:64] = W_msg @ W1[256:280], B2[64] = b_msg @ W1[256:280]
// ============================================================================
__global__ void w2_kernel(const float* __restrict__ W_msg,
                          const float* __restrict__ b_msg,
                          const float* __restrict__ W1) {
    const int r = blockIdx.x;     // 0..64
    const int c = threadIdx.x;    // 0..255
    float acc = 0.f;
#pragma unroll
    for (int j = 0; j < ADDED; j++) {
        const float a = (r < EDGE_DIM) ? W_msg[r * ADDED + j] : b_msg[j];
        acc += a * W1[(long long)(H_DIM + j) * OUT_DIM + c];
    }
    g_B2[r * 256 + c] = acc;
}

// ============================================================================
// Node GEMM: out = relu([h | norm*S | norm*deg] @ [W1a; W2; v] + b1)
// K = 321 padded to 336 (21 k-tiles of 16). Double-buffered tf32 mma.
// Block = 128 rows x 128 cols, 256 threads = 8 warps (4m x 2n).
// ============================================================================
#define ROW_TILES 782     // 782*128 = 100096 >= NN
#define NKT 21            // k-tiles of 16 over padded 336

__global__ __launch_bounds__(256, 2) void node_kernel(
    const float* __restrict__ h,      // [NN, 256]
    const float* __restrict__ norm,   // [NN, 1]
    const float* __restrict__ W1,     // [280, 256]
    const float* __restrict__ b1,     // [256]
    float* __restrict__ out)          // [NN, 256]
{
    __shared__ __align__(16) unsigned As[2][128][20];
    __shared__ __align__(16) unsigned Ws[2][16][136];

    const int tid = threadIdx.x;
    const int wid = tid >> 5;
    const int lane = tid & 31;
    const int g  = lane >> 2;
    const int tg = lane & 3;
    const int wm = wid & 3;
    const int wn = wid >> 2;
    const int rt = blockIdx.x >> 1;
    const int cb = blockIdx.x & 1;
    const int row0 = rt * 128;
    const int col0 = cb * 128;

    const int arow = tid >> 1;
    const int aq   = (tid & 1) * 8;
    const int brow = tid >> 4;
    const int bcol = (tid & 15) * 4;

    const int agrow = row0 + arow;
    const bool arv = (agrow < NN);
    const float nr = arv ? norm[agrow] : 0.f;
    const float nd = arv ? nr * (float)g_deg[agrow] : 0.f;

    float acc[2][8][4];
#pragma unroll
    for (int mt = 0; mt < 2; mt++)
#pragma unroll
        for (int nf = 0; nf < 8; nf++)
#pragma unroll
            for (int i = 0; i < 4; i++) acc[mt][nf][i] = 0.f;

    float4 av[2], bv[2];

    auto fetchA = [&](int ka) -> float4 {
        float4 v = make_float4(0.f, 0.f, 0.f, 0.f);
        if (arv) {
            if (ka < H_DIM) {
                v = *reinterpret_cast<const float4*>(h + (long long)agrow * H_DIM + ka);
            } else if (ka < H_DIM + EDGE_DIM) {
                v = *reinterpret_cast<const float4*>(
                    g_S + (long long)agrow * EDGE_DIM + (ka - H_DIM));
                v.x *= nr; v.y *= nr; v.z *= nr; v.w *= nr;
            } else if (ka == H_DIM + EDGE_DIM) {
                v.x = nd;    // the norm*deg column (320)
            }
        }
        return v;
    };

    auto load_tile = [&](int kt) {
        const int k0 = kt * 16;
        av[0] = fetchA(k0 + aq);
        av[1] = fetchA(k0 + aq + 4);
        const int kb = k0 + brow;
        bv[0] = make_float4(0.f, 0.f, 0.f, 0.f);
        bv[1] = make_float4(0.f, 0.f, 0.f, 0.f);
        if (kb < H_DIM) {
            bv[0] = *reinterpret_cast<const float4*>(
                W1 + (long long)kb * OUT_DIM + col0 + bcol);
            bv[1] = *reinterpret_cast<const float4*>(
                W1 + (long long)kb * OUT_DIM + col0 + bcol + 64);
        } else if (kb <= H_DIM + EDGE_DIM) {
            bv[0] = *reinterpret_cast<const float4*>(
                g_B2 + (kb - H_DIM) * 256 + col0 + bcol);
            bv[1] = *reinterpret_cast<const float4*>(
                g_B2 + (kb - H_DIM) * 256 + col0 + bcol + 64);
        }
    };

    auto cvt_sts = [&](int buf) {
        unsigned* ad = &As[buf][arow][aq];
        ad[0] = cvt_tf32(av[0].x); ad[1] = cvt_tf32(av[0].y);
        ad[2] = cvt_tf32(av[0].z); ad[3] = cvt_tf32(av[0].w);
        ad[4] = cvt_tf32(av[1].x); ad[5] = cvt_tf32(av[1].y);
        ad[6] = cvt_tf32(av[1].z); ad[7] = cvt_tf32(av[1].w);
        unsigned* bd0 = &Ws[buf][brow][bcol];
        bd0[0] = cvt_tf32(bv[0].x); bd0[1] = cvt_tf32(bv[0].y);
        bd0[2] = cvt_tf32(bv[0].z); bd0[3] = cvt_tf32(bv[0].w);
        unsigned* bd1 = &Ws[buf][brow][bcol + 64];
        bd1[0] = cvt_tf32(bv[1].x); bd1[1] = cvt_tf32(bv[1].y);
        bd1[2] = cvt_tf32(bv[1].z); bd1[3] = cvt_tf32(bv[1].w);
    };

    load_tile(0);
    cvt_sts(0);
    __syncthreads();

    for (int kt = 0; kt < NKT; kt++) {
        const int buf = kt & 1;
        if (kt + 1 < NKT) load_tile(kt + 1);

#pragma unroll
        for (int ks = 0; ks < 2; ks++) {
            const int kk = ks * 8;
#pragma unroll
            for (int mt = 0; mt < 2; mt++) {
                const int rb = wm * 32 + mt * 16;
                const unsigned a0 = As[buf][rb + g][kk + tg];
                const unsigned a1 = As[buf][rb + g + 8][kk + tg];
                const unsigned a2 = As[buf][rb + g][kk + tg + 4];
                const unsigned a3 = As[buf][rb + g + 8][kk + tg + 4];
#pragma unroll
                for (int nf = 0; nf < 8; nf++) {
                    const int cc = wn * 64 + nf * 8;
                    const unsigned b0 = Ws[buf][kk + tg][cc + g];
                    const unsigned b1v = Ws[buf][kk + tg + 4][cc + g];
                    mma_tf32(acc[mt][nf][0], acc[mt][nf][1],
                             acc[mt][nf][2], acc[mt][nf][3],
                             a0, a1, a2, a3, b0, b1v);
                }
            }
        }

        if (kt + 1 < NKT) cvt_sts((kt + 1) & 1);
        __syncthreads();
    }

    // epilogue: bias + relu + store
#pragma unroll
    for (int nf = 0; nf < 8; nf++) {
        const int col = col0 + wn * 64 + nf * 8 + 2 * tg;
        const float2 bb = *reinterpret_cast<const float2*>(b1 + col);
#pragma unroll
        for (int mt = 0; mt < 2; mt++) {
            const int r = row0 + wm * 32 + mt * 16 + g;
            if (r < NN) {
                float2 o;
                o.x = fmaxf(acc[mt][nf][0] + bb.x, 0.f);
                o.y = fmaxf(acc[mt][nf][1] + bb.y, 0.f);
                *reinterpret_cast<float2*>(out + (long long)r * OUT_DIM + col) = o;
            }
            const int r2 = r + 8;
            if (r2 < NN) {
                float2 o;
                o.x = fmaxf(acc[mt][nf][2] + bb.x, 0.f);
                o.y = fmaxf(acc[mt][nf][3] + bb.y, 0.f);
                *reinterpret_cast<float2*>(out + (long long)r2 * OUT_DIM + col) = o;
            }
        }
    }
}

// ---------------- launch ----------------
extern "C" void kernel_launch(void* const* d_in, const int* in_sizes, int n_in,
                              void* d_out, int out_size) {
    const float* h         = (const float*)d_in[0];
    const float* edge_feat = (const float*)d_in[1];
    const float* norm      = (const float*)d_in[2];
    const float* W_msg     = (const float*)d_in[3];
    const float* b_msg     = (const float*)d_in[4];
    const float* W1        = (const float*)d_in[5];
    const float* b1        = (const float*)d_in[6];
    const int*   dst_idx   = (const int*)d_in[7];
    float* out = (float*)d_out;

    // CSR build
    zero_deg_kernel<<<(NN + 255) / 256, 256>>>();
    w2_kernel<<<65, 256>>>(W_msg, b_msg, W1);               // independent
    hist_kernel<<<(E_TOTAL + 255) / 256, 256>>>(dst_idx);
    scan1_kernel<<<NBLK, 256>>>();
    scan2_kernel<<<1, 512>>>();
    scan3_kernel<<<NBLK, 256>>>();
    fill_kernel<<<(E_TOTAL + 255) / 256, 256>>>(dst_idx);

    // gather-sum raw edge features (atomic-free)
    gather_kernel<<<(NN + 7) / 8, 256>>>(edge_feat);

    // fused node GEMM: [h | norm*S | norm*deg] @ [W1a; W2; v] + b1, ReLU
    node_kernel<<<ROW_TILES * 2, 256>>>(h, norm, W1, b1, out);
}